// round 16
// baseline (speedup 1.0000x reference)
#include <cuda_runtime.h>
#include <cuda_fp16.h>
#include <math.h>
#include <stdint.h>

// Problem dims (fixed)
#define B_   32
#define S_   512
#define H_   256
#define NH   8
#define HD   32
#define M_   (B_ * S_)     // 16384
#define TOT  (M_ * H_)

#define QK_SCALE_L2E 0.25505654440f     // (1/sqrt(32)) * log2(e)
#define RSQRT2       0.70710678118654752f
#define LN_EPS       1e-5f

// ---------------- scratch ----------------
__device__ __half g_normed[TOT];
__device__ __half g_wih[768 * 256];
__device__ __half g_woh[256 * 256];
__device__ __half g_Q[TOT];     // [b,h,s,d], (q*q+1e-6)*scale*log2e  (>= 0)
__device__ __half g_K[TOT];     // [b,h,s,d], + log(radial_mask)
__device__ __half g_V[TOT];     // [b,h,s,d]
__device__ __half g_attn[TOT];  // [b,s,H]
__device__ float    g_lr[M_];
__device__ unsigned g_maxkd[B_ * NH * HD];   // order-preserving float keys

// ---------------- helpers ----------------
__device__ __forceinline__ void mma_f16(float* d, const unsigned* a, const unsigned* b) {
    asm("mma.sync.aligned.m16n8k16.row.col.f32.f16.f16.f32 "
        "{%0,%1,%2,%3},{%4,%5,%6,%7},{%8,%9},{%0,%1,%2,%3};"
        : "+f"(d[0]), "+f"(d[1]), "+f"(d[2]), "+f"(d[3])
        : "r"(a[0]), "r"(a[1]), "r"(a[2]), "r"(a[3]), "r"(b[0]), "r"(b[1]));
}
__device__ __forceinline__ void ldsm4(unsigned* r, uint32_t addr) {
    asm volatile("ldmatrix.sync.aligned.m8n8.x4.shared.b16 {%0,%1,%2,%3}, [%4];"
        : "=r"(r[0]), "=r"(r[1]), "=r"(r[2]), "=r"(r[3]) : "r"(addr));
}
__device__ __forceinline__ void ldsm4t(unsigned* r, uint32_t addr) {
    asm volatile("ldmatrix.sync.aligned.m8n8.x4.trans.shared.b16 {%0,%1,%2,%3}, [%4];"
        : "=r"(r[0]), "=r"(r[1]), "=r"(r[2]), "=r"(r[3]) : "r"(addr));
}
__device__ __forceinline__ unsigned packh2(float lo, float hi) {
    __half2 h = __floats2half2_rn(lo, hi);
    return *(unsigned*)&h;
}
__device__ __forceinline__ unsigned ex2h2(unsigned x) {
    unsigned y;
    asm("ex2.approx.f16x2 %0, %1;" : "=r"(y) : "r"(x));
    return y;
}
__device__ __forceinline__ unsigned ldu32(const __half* p) {
    return *(const unsigned*)p;
}
__device__ __forceinline__ void cp16s(uint32_t saddr, const void* gptr) {
    asm volatile("cp.async.cg.shared.global [%0], [%1], 16;" :: "r"(saddr), "l"(gptr));
}
#define CP_COMMIT() asm volatile("cp.async.commit_group;")
#define CP_WAIT2()  asm volatile("cp.async.wait_group 2;")
#define CP_WAIT3()  asm volatile("cp.async.wait_group 3;")

// order-preserving float<->uint key
__device__ __forceinline__ unsigned fkey(float f) {
    unsigned b = __float_as_uint(f);
    return (b & 0x80000000u) ? ~b : (b | 0x80000000u);
}
__device__ __forceinline__ float funkey(unsigned k) {
    unsigned b = (k & 0x80000000u) ? (k & 0x7fffffffu) : ~k;
    return __uint_as_float(b);
}

// ---------------- LayerNorm + fused weight conversion + maxk init ----------------
__global__ __launch_bounds__(256) void ln_conv_kernel(
    const float* __restrict__ x, const float* __restrict__ gamma,
    const float* __restrict__ beta, const float* __restrict__ rmask,
    const float* __restrict__ wi, const float* __restrict__ wo)
{
    int warp = threadIdx.x >> 5, lane = threadIdx.x & 31;
    int row  = blockIdx.x * 8 + warp;

    int gi = blockIdx.x * 256 + threadIdx.x;
    const int N1 = 768 * 256 / 2;
    const int N2 = 256 * 256 / 2;
    if (gi < B_ * NH * HD) g_maxkd[gi] = 0u;
    if (gi < N1) {
        float2 v = ((const float2*)wi)[gi];
        ((__half2*)g_wih)[gi] = __floats2half2_rn(v.x, v.y);
    } else if (gi < N1 + N2) {
        int j = gi - N1;
        float2 v = ((const float2*)wo)[j];
        ((__half2*)g_woh)[j] = __floats2half2_rn(v.x, v.y);
    }

    const float2* xr = (const float2*)(x + row * H_);
    const float2* g2 = (const float2*)gamma;
    const float2* b2 = (const float2*)beta;

    float2 v[4];
    float sum = 0.f, sq = 0.f;
#pragma unroll
    for (int k = 0; k < 4; k++) {
        float2 t = xr[lane + 32 * k];
        v[k] = t;
        sum += t.x + t.y;
        sq  += t.x * t.x + t.y * t.y;
    }
#pragma unroll
    for (int o = 16; o > 0; o >>= 1) {
        sum += __shfl_xor_sync(0xffffffffu, sum, o);
        sq  += __shfl_xor_sync(0xffffffffu, sq,  o);
    }
    float mu = sum * (1.f / H_);
    float var = sq * (1.f / H_) - mu * mu;
    float rstd = rsqrtf(var + LN_EPS);

    __half2* nr = (__half2*)(g_normed + row * H_);
#pragma unroll
    for (int k = 0; k < 4; k++) {
        int idx = lane + 32 * k;
        float2 gv = g2[idx], bv = b2[idx];
        nr[idx] = __floats2half2_rn(
            (v[k].x - mu) * rstd * gv.x + bv.x,
            (v[k].y - mu) * rstd * gv.y + bv.y);
    }
    if (lane == 0) g_lr[row] = logf(rmask[row]);
}

// ---------------- fp16 MMA GEMM (NT): 64x128 CTA tile, 4-buffer depth-3 cp.async ----------------
// 8 warps of 32x32 (wm 2 x wn 4). A stage 9KB + B stage 18KB; 4 stages = 108KB, 2 CTAs/SM.
#define SSTRH 72
#define ATILEH (64 * SSTRH)     // A stage halves
#define BTILEH (128 * SSTRH)    // B stage halves

template <int MODE>
__global__ __launch_bounds__(256, 2) void gemm_f16(
    const float* __restrict__ extra, float* __restrict__ C)
{
    extern __shared__ __half smh[];
    __half* As = smh;                  // [4][ATILEH]
    __half* Bs = smh + 4 * ATILEH;     // [4][BTILEH]

    const __half* A    = (MODE == 1) ? g_normed : g_attn;
    const __half* Bmat = (MODE == 1) ? g_wih : g_woh;
    const int K = 256;

    int tid = threadIdx.x;
    int wid = tid >> 5, lane = tid & 31;
    int g = lane >> 2, t = lane & 3;
    int wm = wid >> 2, wn = wid & 3;        // 2 x 4 warps of 32x32
    int brow = blockIdx.y, bcol = blockIdx.x;

    int c8  = tid & 7;
    int rwg = tid >> 3;                     // 0..31

    int arow_lm = (lane & 7) + ((lane >> 3) & 1) * 8;
    int acol_lm = (lane >> 4) * 8;
    int brow_lm = (lane & 7) + (lane >> 4) * 8;
    int bcol_lm = ((lane >> 3) & 1) * 8;

    const __half* Agb = A    + (size_t)(brow * 64) * K;
    const __half* Bgb = Bmat + (size_t)(bcol * 128) * K;
    uint32_t asBase = (uint32_t)__cvta_generic_to_shared(As);
    uint32_t bsBase = (uint32_t)__cvta_generic_to_shared(Bs);

    float dacc[2][4][4];
#pragma unroll
    for (int i = 0; i < 2; i++)
#pragma unroll
        for (int j = 0; j < 4; j++)
#pragma unroll
            for (int c = 0; c < 4; c++) dacc[i][j][c] = 0.f;

#define STAGE(kt_, buf_) do { \
    int _kb = (kt_) * 64; \
    uint32_t _ab = asBase + (uint32_t)(buf_) * (ATILEH * 2); \
    uint32_t _bb = bsBase + (uint32_t)(buf_) * (BTILEH * 2); \
    _Pragma("unroll") \
    for (int _i = 0; _i < 2; _i++) { \
        int _row = rwg + _i * 32; \
        cp16s(_ab + (uint32_t)_row * (SSTRH * 2) + (uint32_t)c8 * 16, \
              Agb + (size_t)_row * K + _kb + c8 * 8); \
    } \
    _Pragma("unroll") \
    for (int _i = 0; _i < 4; _i++) { \
        int _row = rwg + _i * 32; \
        cp16s(_bb + (uint32_t)_row * (SSTRH * 2) + (uint32_t)c8 * 16, \
              Bgb + (size_t)_row * K + _kb + c8 * 8); \
    } \
} while (0)

    STAGE(0, 0); CP_COMMIT();
    STAGE(1, 1); CP_COMMIT();
    STAGE(2, 2); CP_COMMIT();

#pragma unroll
    for (int kt = 0; kt < 4; kt++) {
        if (kt + 3 < 4) STAGE(kt + 3, (kt + 3) & 3);
        CP_COMMIT();       // empty when no prefetch: keeps group counts aligned
        CP_WAIT3();        // retires exactly group kt
        __syncthreads();

        uint32_t abuf = asBase + (uint32_t)(kt & 3) * (ATILEH * 2);
        uint32_t bbuf = bsBase + (uint32_t)(kt & 3) * (BTILEH * 2);
#pragma unroll
        for (int ks = 0; ks < 4; ks++) {
            unsigned af[2][4], bf[4][2];
#pragma unroll
            for (int mi = 0; mi < 2; mi++)
                ldsm4(af[mi], abuf + (uint32_t)((wm * 32 + mi * 16 + arow_lm) * SSTRH
                                               + ks * 16 + acol_lm) * 2);
#pragma unroll
            for (int nig = 0; nig < 2; nig++) {
                unsigned r[4];
                ldsm4(r, bbuf + (uint32_t)((wn * 32 + nig * 16 + brow_lm) * SSTRH
                                           + ks * 16 + bcol_lm) * 2);
                bf[nig * 2][0] = r[0]; bf[nig * 2][1] = r[1];
                bf[nig * 2 + 1][0] = r[2]; bf[nig * 2 + 1][1] = r[3];
            }
#pragma unroll
            for (int mi = 0; mi < 2; mi++)
#pragma unroll
                for (int ni = 0; ni < 4; ni++)
                    mma_f16(dacc[mi][ni], af[mi], bf[ni]);
        }
        __syncthreads();
    }
#undef STAGE

    if (MODE == 1) {
        int region = (bcol * 128) >> 8;   // 0=q 1=k 2=v (uniform per CTA)
        int hh = ((bcol & 1) << 2) + wn;
        float cmax[4][2];
#pragma unroll
        for (int ni = 0; ni < 4; ni++) { cmax[ni][0] = -1e30f; cmax[ni][1] = -1e30f; }

#pragma unroll
        for (int mi = 0; mi < 2; mi++) {
            int r0 = brow * 64 + wm * 32 + mi * 16 + g;
            int r1 = r0 + 8;
            int b = r0 >> 9, s0 = r0 & 511, s1 = r1 & 511;
            __half* dst = (region == 0) ? g_Q : (region == 1) ? g_K : g_V;
            float lr0 = (region == 1) ? g_lr[r0] : 0.f;
            float lr1 = (region == 1) ? g_lr[r1] : 0.f;
            __half* p0 = dst + ((size_t)(b * 8 + hh) * S_ + s0) * HD;
            __half* p1 = dst + ((size_t)(b * 8 + hh) * S_ + s1) * HD;
#pragma unroll
            for (int ni = 0; ni < 4; ni++) {
                int dcol = ni * 8 + 2 * t;
                float v0 = dacc[mi][ni][0], v1 = dacc[mi][ni][1];
                float v2 = dacc[mi][ni][2], v3 = dacc[mi][ni][3];
                if (region == 0) {
                    v0 = (v0 * v0 + 1e-6f) * QK_SCALE_L2E;
                    v1 = (v1 * v1 + 1e-6f) * QK_SCALE_L2E;
                    v2 = (v2 * v2 + 1e-6f) * QK_SCALE_L2E;
                    v3 = (v3 * v3 + 1e-6f) * QK_SCALE_L2E;
                } else if (region == 1) {
                    v0 += lr0; v1 += lr0; v2 += lr1; v3 += lr1;
                    cmax[ni][0] = fmaxf(cmax[ni][0], fmaxf(v0, v2));
                    cmax[ni][1] = fmaxf(cmax[ni][1], fmaxf(v1, v3));
                }
                *(__half2*)(p0 + dcol) = __floats2half2_rn(v0, v1);
                *(__half2*)(p1 + dcol) = __floats2half2_rn(v2, v3);
            }
        }

        if (region == 1) {
#pragma unroll
            for (int ni = 0; ni < 4; ni++) {
#pragma unroll
                for (int o = 4; o <= 16; o <<= 1) {
                    cmax[ni][0] = fmaxf(cmax[ni][0], __shfl_xor_sync(0xffffffffu, cmax[ni][0], o));
                    cmax[ni][1] = fmaxf(cmax[ni][1], __shfl_xor_sync(0xffffffffu, cmax[ni][1], o));
                }
            }
            if (g == 0) {
                int b = (brow * 64) >> 9;
                unsigned* mk = g_maxkd + (size_t)(b * 8 + hh) * HD;
#pragma unroll
                for (int ni = 0; ni < 4; ni++) {
                    atomicMax(&mk[ni * 8 + 2 * t],     fkey(cmax[ni][0]));
                    atomicMax(&mk[ni * 8 + 2 * t + 1], fkey(cmax[ni][1]));
                }
            }
        }
    } else {
#pragma unroll
        for (int mi = 0; mi < 2; mi++) {
            int r0 = brow * 64 + wm * 32 + mi * 16 + g;
            int r1 = r0 + 8;
            int cbase = bcol * 128 + wn * 32;
            const float* in0 = extra + (size_t)r0 * H_ + cbase;
            const float* in1 = extra + (size_t)r1 * H_ + cbase;
            float* o0 = C + (size_t)r0 * H_ + cbase;
            float* o1 = C + (size_t)r1 * H_ + cbase;
#pragma unroll
            for (int ni = 0; ni < 4; ni++) {
                int dcol = ni * 8 + 2 * t;
                float2 i0 = *(const float2*)(in0 + dcol);
                float2 i1 = *(const float2*)(in1 + dcol);
                *(float2*)(o0 + dcol) = make_float2(
                    (dacc[mi][ni][0] + i0.x) * RSQRT2, (dacc[mi][ni][1] + i0.y) * RSQRT2);
                *(float2*)(o1 + dcol) = make_float2(
                    (dacc[mi][ni][2] + i1.x) * RSQRT2, (dacc[mi][ni][3] + i1.y) * RSQRT2);
            }
        }
    }
}

// ---------------- attention: fp16 mma, static bound, 4-stage cp.async (R12 proven) ----------------
#define ASTR 40

__global__ __launch_bounds__(256) void attn_f16_kernel()
{
    __shared__ __half Ks[4][32 * ASTR];
    __shared__ __half Vs[4][32 * ASTR];

    int tid = threadIdx.x;
    int wid = tid >> 5, lane = tid & 31;
    int g = lane >> 2, t = lane & 3;
    int qhalf = blockIdx.x & 1, bh = blockIdx.x >> 1;
    int b = bh >> 3, h = bh & 7;
    int qbase = qhalf * 256 + wid * 32;

    int brow_lm = (lane & 7) + (lane >> 4) * 8;      // K (non-trans)
    int bcol_lm = ((lane >> 3) & 1) * 8;
    int trow_lm = lane & 15;                         // V (trans): key row
    int tcol_lm = (lane >> 4) * 8;                   // +8 n col

    // Q fragments resident
    const __half* Qg = g_Q + ((size_t)bh * S_ + qbase) * HD;
    unsigned qf[2][2][4];
#pragma unroll
    for (int mi = 0; mi < 2; mi++) {
        int r = mi * 16 + g;
#pragma unroll
        for (int ks = 0; ks < 2; ks++) {
            qf[mi][ks][0] = ldu32(&Qg[r * HD + ks * 16 + 2 * t]);
            qf[mi][ks][1] = ldu32(&Qg[(r + 8) * HD + ks * 16 + 2 * t]);
            qf[mi][ks][2] = ldu32(&Qg[r * HD + ks * 16 + 2 * t + 8]);
            qf[mi][ks][3] = ldu32(&Qg[(r + 8) * HD + ks * 16 + 2 * t + 8]);
        }
    }

    // static row-max bound
    float mrow[4];
    {
        const unsigned* mku = g_maxkd + bh * HD;
        float m0[2] = {0.f, 0.f}, m1[2] = {0.f, 0.f};
#pragma unroll
        for (int ks = 0; ks < 2; ks++) {
            float mkA0 = funkey(mku[ks * 16 + 2 * t]);
            float mkA1 = funkey(mku[ks * 16 + 2 * t + 1]);
            float mkB0 = funkey(mku[ks * 16 + 2 * t + 8]);
            float mkB1 = funkey(mku[ks * 16 + 2 * t + 9]);
#pragma unroll
            for (int mi = 0; mi < 2; mi++) {
                float2 qa = __half22float2(*(__half2*)&qf[mi][ks][0]);
                float2 qb = __half22float2(*(__half2*)&qf[mi][ks][2]);
                float2 qc = __half22float2(*(__half2*)&qf[mi][ks][1]);
                float2 qd = __half22float2(*(__half2*)&qf[mi][ks][3]);
                m0[mi] += qa.x * mkA0 + qa.y * mkA1 + qb.x * mkB0 + qb.y * mkB1;
                m1[mi] += qc.x * mkA0 + qc.y * mkA1 + qd.x * mkB0 + qd.y * mkB1;
            }
        }
#pragma unroll
        for (int o = 1; o <= 2; o <<= 1) {
#pragma unroll
            for (int mi = 0; mi < 2; mi++) {
                m0[mi] += __shfl_xor_sync(0xffffffffu, m0[mi], o);
                m1[mi] += __shfl_xor_sync(0xffffffffu, m1[mi], o);
            }
        }
        mrow[0] = m0[0]; mrow[1] = m1[0]; mrow[2] = m0[1]; mrow[3] = m1[1];
    }

    float oacc[2][4][4];
#pragma unroll
    for (int mi = 0; mi < 2; mi++)
#pragma unroll
        for (int nd = 0; nd < 4; nd++)
#pragma unroll
            for (int c = 0; c < 4; c++) oacc[mi][nd][c] = 0.f;
    float lacc[2][4];
#pragma unroll
    for (int mi = 0; mi < 2; mi++)
#pragma unroll
        for (int c = 0; c < 4; c++) lacc[mi][c] = 0.f;

    const unsigned ONES2[2] = {0x3C003C00u, 0x3C003C00u};

    int mat = tid >> 7;           // 0 = K, 1 = V
    int lrw = (tid >> 2) & 31;
    int c4  = tid & 3;
    const __half* Kg = g_K + (size_t)bh * S_ * HD;
    const __half* Vg = g_V + (size_t)bh * S_ * HD;
    const __half* src = (mat == 0) ? Kg : Vg;
    uint32_t ksb = (uint32_t)__cvta_generic_to_shared(&Ks[0][0]);
    uint32_t vsb = (uint32_t)__cvta_generic_to_shared(&Vs[0][0]);
    uint32_t dstb = (mat == 0) ? ksb : vsb;

#define ASTAGE(kt_) do { \
    uint32_t _soff = (uint32_t)((kt_) & 3) * (32 * ASTR * 2) + (uint32_t)lrw * (ASTR * 2) + (uint32_t)c4 * 16; \
    cp16s(dstb + _soff, src + (size_t)((kt_) * 32 + lrw) * HD + c4 * 8); \
} while (0)

    ASTAGE(0); CP_COMMIT();
    ASTAGE(1); CP_COMMIT();
    ASTAGE(2); CP_COMMIT();

#pragma unroll 4
    for (int kt = 0; kt < 16; kt++) {
        CP_WAIT2();
        __syncthreads();
        if (kt + 3 < 16) ASTAGE(kt + 3);
        CP_COMMIT();

        uint32_t kbuf = ksb + (uint32_t)(kt & 3) * (32 * ASTR * 2);
        uint32_t vbuf = vsb + (uint32_t)(kt & 3) * (32 * ASTR * 2);

        // ---- QK^T with -m folded into accumulator init ----
        float sacc[2][4][4];
#pragma unroll
        for (int mi = 0; mi < 2; mi++)
#pragma unroll
            for (int ni = 0; ni < 4; ni++) {
                sacc[mi][ni][0] = -mrow[2 * mi];
                sacc[mi][ni][1] = -mrow[2 * mi];
                sacc[mi][ni][2] = -mrow[2 * mi + 1];
                sacc[mi][ni][3] = -mrow[2 * mi + 1];
            }

#pragma unroll
        for (int ks = 0; ks < 2; ks++) {
            unsigned kb[4][2];
#pragma unroll
            for (int nig = 0; nig < 2; nig++) {
                unsigned r[4];
                ldsm4(r, kbuf + (uint32_t)((nig * 16 + brow_lm) * ASTR + ks * 16 + bcol_lm) * 2);
                kb[nig * 2][0] = r[0]; kb[nig * 2][1] = r[1];
                kb[nig * 2 + 1][0] = r[2]; kb[nig * 2 + 1][1] = r[3];
            }
#pragma unroll
            for (int mi = 0; mi < 2; mi++)
#pragma unroll
                for (int ni = 0; ni < 4; ni++)
                    mma_f16(sacc[mi][ni], qf[mi][ks], kb[ni]);
        }

        // ---- exp (f16x2); result IS the PV A-frag ----
        unsigned p01[2][4], p23[2][4];
#pragma unroll
        for (int mi = 0; mi < 2; mi++)
#pragma unroll
            for (int ni = 0; ni < 4; ni++) {
                p01[mi][ni] = ex2h2(packh2(sacc[mi][ni][0], sacc[mi][ni][1]));
                p23[mi][ni] = ex2h2(packh2(sacc[mi][ni][2], sacc[mi][ni][3]));
            }

        // ---- PV (ldmatrix.trans B-frags from [s][d] V tile) + l-ones-mma ----
#pragma unroll
        for (int ks = 0; ks < 2; ks++) {
            unsigned vb[4][2];
#pragma unroll
            for (int ng = 0; ng < 2; ng++) {
                unsigned r[4];
                ldsm4t(r, vbuf + (uint32_t)((ks * 16 + trow_lm) * ASTR + ng * 16 + tcol_lm) * 2);
                vb[ng * 2][0] = r[0]; vb[ng * 2][1] = r[1];
                vb[ng * 2 + 1][0] = r[2]; vb[ng * 2 + 1][1] = r[3];
            }
#pragma unroll
            for (int mi = 0; mi < 2; mi++) {
                unsigned pa_[4];
                pa_[0] = p01[mi][2 * ks];
                pa_[1] = p23[mi][2 * ks];
                pa_[2] = p01[mi][2 * ks + 1];
                pa_[3] = p23[mi][2 * ks + 1];
#pragma unroll
                for (int nd = 0; nd < 4; nd++)
                    mma_f16(oacc[mi][nd], pa_, vb[nd]);
                mma_f16(lacc[mi], pa_, ONES2);
            }
        }
    }
#undef ASTAGE

    // finalize
#pragma unroll
    for (int r = 0; r < 4; r++) {
        int mi = r >> 1, cb = (r & 1) * 2;
        float inv = 1.f / lacc[mi][cb];
        int row = qbase + (r >> 1) * 16 + (r & 1) * 8 + g;
        __half* op = g_attn + ((size_t)b * S_ + row) * H_ + h * HD;
#pragma unroll
        for (int nd = 0; nd < 4; nd++) {
            *(__half2*)(op + nd * 8 + 2 * t) = __floats2half2_rn(
                oacc[mi][nd][cb] * inv, oacc[mi][nd][cb + 1] * inv);
        }
    }
}

// ---------------- launch ----------------
extern "C" void kernel_launch(void* const* d_in, const int* in_sizes, int n_in,
                              void* d_out, int out_size)
{
    const float* inputs = (const float*)d_in[0];
    const float* rmask  = (const float*)d_in[1];
    const float* w_in   = (const float*)d_in[2];
    const float* w_out  = (const float*)d_in[3];
    const float* gamma  = (const float*)d_in[4];
    const float* beta   = (const float*)d_in[5];
    float* out = (float*)d_out;

    const int gemm_smem = 4 * (ATILEH + BTILEH) * (int)sizeof(__half);   // 110592 B
    cudaFuncSetAttribute(gemm_f16<1>, cudaFuncAttributeMaxDynamicSharedMemorySize, gemm_smem);
    cudaFuncSetAttribute(gemm_f16<2>, cudaFuncAttributeMaxDynamicSharedMemorySize, gemm_smem);

    ln_conv_kernel<<<M_ / 8, 256>>>(inputs, gamma, beta, rmask, w_in, w_out);
    gemm_f16<1><<<dim3(6, M_ / 64), 256, gemm_smem>>>(nullptr, nullptr);
    attn_f16_kernel<<<512, 256>>>();
    gemm_f16<2><<<dim3(2, M_ / 64), 256, gemm_smem>>>(inputs, out);
}

// round 17
// speedup vs baseline: 1.0556x; 1.0556x over previous
#include <cuda_runtime.h>
#include <cuda_fp16.h>
#include <math.h>
#include <stdint.h>

// Problem dims (fixed)
#define B_   32
#define S_   512
#define H_   256
#define NH   8
#define HD   32
#define M_   (B_ * S_)     // 16384
#define TOT  (M_ * H_)

#define QK_SCALE_L2E 0.25505654440f     // (1/sqrt(32)) * log2(e)
#define RSQRT2       0.70710678118654752f
#define LN_EPS       1e-5f

// ---------------- scratch ----------------
__device__ __half g_normed[TOT];
__device__ __half g_wih[768 * 256];
__device__ __half g_woh[256 * 256];
__device__ __half g_Q[TOT];     // [b,h,s,d], (q*q+1e-6)*scale*log2e  (>= 0)
__device__ __half g_K[TOT];     // [b,h,s,d], + log(radial_mask)
__device__ __half g_V[TOT];     // [b,h,s,d]
__device__ __half g_attn[TOT];  // [b,s,H]
__device__ float    g_lr[M_];
__device__ unsigned g_maxkd[B_ * NH * HD];   // order-preserving float keys

// ---------------- helpers ----------------
__device__ __forceinline__ void mma_f16(float* d, const unsigned* a, const unsigned* b) {
    asm("mma.sync.aligned.m16n8k16.row.col.f32.f16.f16.f32 "
        "{%0,%1,%2,%3},{%4,%5,%6,%7},{%8,%9},{%0,%1,%2,%3};"
        : "+f"(d[0]), "+f"(d[1]), "+f"(d[2]), "+f"(d[3])
        : "r"(a[0]), "r"(a[1]), "r"(a[2]), "r"(a[3]), "r"(b[0]), "r"(b[1]));
}
__device__ __forceinline__ void ldsm4(unsigned* r, uint32_t addr) {
    asm volatile("ldmatrix.sync.aligned.m8n8.x4.shared.b16 {%0,%1,%2,%3}, [%4];"
        : "=r"(r[0]), "=r"(r[1]), "=r"(r[2]), "=r"(r[3]) : "r"(addr));
}
__device__ __forceinline__ void ldsm4t(unsigned* r, uint32_t addr) {
    asm volatile("ldmatrix.sync.aligned.m8n8.x4.trans.shared.b16 {%0,%1,%2,%3}, [%4];"
        : "=r"(r[0]), "=r"(r[1]), "=r"(r[2]), "=r"(r[3]) : "r"(addr));
}
__device__ __forceinline__ unsigned packh2(float lo, float hi) {
    __half2 h = __floats2half2_rn(lo, hi);
    return *(unsigned*)&h;
}
__device__ __forceinline__ unsigned ex2h2(unsigned x) {
    unsigned y;
    asm("ex2.approx.f16x2 %0, %1;" : "=r"(y) : "r"(x));
    return y;
}
__device__ __forceinline__ unsigned ldu32(const __half* p) {
    return *(const unsigned*)p;
}
__device__ __forceinline__ void cp16s(uint32_t saddr, const void* gptr) {
    asm volatile("cp.async.cg.shared.global [%0], [%1], 16;" :: "r"(saddr), "l"(gptr));
}
#define CP_COMMIT() asm volatile("cp.async.commit_group;")
#define CP_WAIT1()  asm volatile("cp.async.wait_group 1;")
#define CP_WAIT2()  asm volatile("cp.async.wait_group 2;")

// order-preserving float<->uint key
__device__ __forceinline__ unsigned fkey(float f) {
    unsigned b = __float_as_uint(f);
    return (b & 0x80000000u) ? ~b : (b | 0x80000000u);
}
__device__ __forceinline__ float funkey(unsigned k) {
    unsigned b = (k & 0x80000000u) ? (k & 0x7fffffffu) : ~k;
    return __uint_as_float(b);
}

// ---------------- LayerNorm + fused weight conversion + maxk init ----------------
__global__ __launch_bounds__(256) void ln_conv_kernel(
    const float* __restrict__ x, const float* __restrict__ gamma,
    const float* __restrict__ beta, const float* __restrict__ rmask,
    const float* __restrict__ wi, const float* __restrict__ wo)
{
    int warp = threadIdx.x >> 5, lane = threadIdx.x & 31;
    int row  = blockIdx.x * 8 + warp;

    int gi = blockIdx.x * 256 + threadIdx.x;
    const int N1 = 768 * 256 / 2;
    const int N2 = 256 * 256 / 2;
    if (gi < B_ * NH * HD) g_maxkd[gi] = 0u;
    if (gi < N1) {
        float2 v = ((const float2*)wi)[gi];
        ((__half2*)g_wih)[gi] = __floats2half2_rn(v.x, v.y);
    } else if (gi < N1 + N2) {
        int j = gi - N1;
        float2 v = ((const float2*)wo)[j];
        ((__half2*)g_woh)[j] = __floats2half2_rn(v.x, v.y);
    }

    const float2* xr = (const float2*)(x + row * H_);
    const float2* g2 = (const float2*)gamma;
    const float2* b2 = (const float2*)beta;

    float2 v[4];
    float sum = 0.f, sq = 0.f;
#pragma unroll
    for (int k = 0; k < 4; k++) {
        float2 t = xr[lane + 32 * k];
        v[k] = t;
        sum += t.x + t.y;
        sq  += t.x * t.x + t.y * t.y;
    }
#pragma unroll
    for (int o = 16; o > 0; o >>= 1) {
        sum += __shfl_xor_sync(0xffffffffu, sum, o);
        sq  += __shfl_xor_sync(0xffffffffu, sq,  o);
    }
    float mu = sum * (1.f / H_);
    float var = sq * (1.f / H_) - mu * mu;
    float rstd = rsqrtf(var + LN_EPS);

    __half2* nr = (__half2*)(g_normed + row * H_);
#pragma unroll
    for (int k = 0; k < 4; k++) {
        int idx = lane + 32 * k;
        float2 gv = g2[idx], bv = b2[idx];
        nr[idx] = __floats2half2_rn(
            (v[k].x - mu) * rstd * gv.x + bv.x,
            (v[k].y - mu) * rstd * gv.y + bv.y);
    }
    if (lane == 0) g_lr[row] = logf(rmask[row]);
}

// ---------------- fp16 MMA GEMM (NT): 3-stage cp.async, single barrier/tile,
// ---------------- prefetch-first, ldmatrix frags, 2 CTAs/SM ----------------
#define SSTRH 72
#define TILEH (128 * SSTRH)

template <int MODE>
__global__ __launch_bounds__(256, 2) void gemm_f16(
    const float* __restrict__ extra, float* __restrict__ C)
{
    extern __shared__ __half smh[];
    __half* As = smh;                 // [3][TILEH]
    __half* Bs = smh + 3 * TILEH;     // [3][TILEH]

    const __half* A    = (MODE == 1) ? g_normed : g_attn;
    const __half* Bmat = (MODE == 1) ? g_wih : g_woh;
    const int K = 256;

    int tid = threadIdx.x;
    int wid = tid >> 5, lane = tid & 31;
    int g = lane >> 2, t = lane & 3;
    int wm = wid >> 2, wn = wid & 3;
    int brow = blockIdx.y, bcol = blockIdx.x;

    int c8  = tid & 7;
    int rwg = tid >> 3;

    int arow_lm = (lane & 7) + ((lane >> 3) & 1) * 8;
    int acol_lm = (lane >> 4) * 8;
    int brow_lm = (lane & 7) + (lane >> 4) * 8;
    int bcol_lm = ((lane >> 3) & 1) * 8;

    const __half* Agb = A    + (size_t)(brow * 128) * K;
    const __half* Bgb = Bmat + (size_t)(bcol * 128) * K;
    uint32_t asBase = (uint32_t)__cvta_generic_to_shared(As);
    uint32_t bsBase = (uint32_t)__cvta_generic_to_shared(Bs);

    float dacc[4][4][4];
#pragma unroll
    for (int i = 0; i < 4; i++)
#pragma unroll
        for (int j = 0; j < 4; j++)
#pragma unroll
            for (int c = 0; c < 4; c++) dacc[i][j][c] = 0.f;

#define STAGE(kt_, buf_) do { \
    int _kb = (kt_) * 64; \
    uint32_t _ab = asBase + (uint32_t)(buf_) * (TILEH * 2); \
    uint32_t _bb = bsBase + (uint32_t)(buf_) * (TILEH * 2); \
    _Pragma("unroll") \
    for (int _i = 0; _i < 4; _i++) { \
        int _row = rwg + _i * 32; \
        uint32_t _off = (uint32_t)_row * (SSTRH * 2) + (uint32_t)c8 * 16; \
        cp16s(_ab + _off, Agb + (size_t)_row * K + _kb + c8 * 8); \
        cp16s(_bb + _off, Bgb + (size_t)_row * K + _kb + c8 * 8); \
    } \
} while (0)

    STAGE(0, 0); CP_COMMIT();
    STAGE(1, 1); CP_COMMIT();

#pragma unroll
    for (int kt = 0; kt < 4; kt++) {
        CP_WAIT1();
        __syncthreads();
        // prefetch kt+2 into buffer (kt+2)%3 — last read at kt-1, safe behind barrier
        if (kt + 2 < 4) STAGE(kt + 2, (kt + 2) % 3);
        CP_COMMIT();

        uint32_t abuf = asBase + (uint32_t)(kt % 3) * (TILEH * 2);
        uint32_t bbuf = bsBase + (uint32_t)(kt % 3) * (TILEH * 2);
#pragma unroll
        for (int ks = 0; ks < 4; ks++) {
            unsigned af[4][4], bf[4][2];
#pragma unroll
            for (int mi = 0; mi < 4; mi++)
                ldsm4(af[mi], abuf + (uint32_t)((wm * 64 + mi * 16 + arow_lm) * SSTRH
                                               + ks * 16 + acol_lm) * 2);
#pragma unroll
            for (int nig = 0; nig < 2; nig++) {
                unsigned r[4];
                ldsm4(r, bbuf + (uint32_t)((wn * 32 + nig * 16 + brow_lm) * SSTRH
                                           + ks * 16 + bcol_lm) * 2);
                bf[nig * 2][0] = r[0]; bf[nig * 2][1] = r[1];
                bf[nig * 2 + 1][0] = r[2]; bf[nig * 2 + 1][1] = r[3];
            }
#pragma unroll
            for (int mi = 0; mi < 4; mi++)
#pragma unroll
                for (int ni = 0; ni < 4; ni++)
                    mma_f16(dacc[mi][ni], af[mi], bf[ni]);
        }
    }
#undef STAGE

    if (MODE == 1) {
        int region = (bcol * 128) >> 8;   // 0=q 1=k 2=v (uniform per CTA)
        int hh = ((bcol & 1) << 2) + wn;
        float cmax[4][2];
#pragma unroll
        for (int ni = 0; ni < 4; ni++) { cmax[ni][0] = -1e30f; cmax[ni][1] = -1e30f; }

#pragma unroll
        for (int mi = 0; mi < 4; mi++) {
            int r0 = brow * 128 + wm * 64 + mi * 16 + g;
            int r1 = r0 + 8;
            int b = r0 >> 9, s0 = r0 & 511, s1 = r1 & 511;
            __half* dst = (region == 0) ? g_Q : (region == 1) ? g_K : g_V;
            float lr0 = (region == 1) ? g_lr[r0] : 0.f;
            float lr1 = (region == 1) ? g_lr[r1] : 0.f;
            __half* p0 = dst + ((size_t)(b * 8 + hh) * S_ + s0) * HD;
            __half* p1 = dst + ((size_t)(b * 8 + hh) * S_ + s1) * HD;
#pragma unroll
            for (int ni = 0; ni < 4; ni++) {
                int dcol = ni * 8 + 2 * t;
                float v0 = dacc[mi][ni][0], v1 = dacc[mi][ni][1];
                float v2 = dacc[mi][ni][2], v3 = dacc[mi][ni][3];
                if (region == 0) {
                    v0 = (v0 * v0 + 1e-6f) * QK_SCALE_L2E;
                    v1 = (v1 * v1 + 1e-6f) * QK_SCALE_L2E;
                    v2 = (v2 * v2 + 1e-6f) * QK_SCALE_L2E;
                    v3 = (v3 * v3 + 1e-6f) * QK_SCALE_L2E;
                } else if (region == 1) {
                    v0 += lr0; v1 += lr0; v2 += lr1; v3 += lr1;
                    cmax[ni][0] = fmaxf(cmax[ni][0], fmaxf(v0, v2));
                    cmax[ni][1] = fmaxf(cmax[ni][1], fmaxf(v1, v3));
                }
                *(__half2*)(p0 + dcol) = __floats2half2_rn(v0, v1);
                *(__half2*)(p1 + dcol) = __floats2half2_rn(v2, v3);
            }
        }

        if (region == 1) {
#pragma unroll
            for (int ni = 0; ni < 4; ni++) {
#pragma unroll
                for (int o = 4; o <= 16; o <<= 1) {
                    cmax[ni][0] = fmaxf(cmax[ni][0], __shfl_xor_sync(0xffffffffu, cmax[ni][0], o));
                    cmax[ni][1] = fmaxf(cmax[ni][1], __shfl_xor_sync(0xffffffffu, cmax[ni][1], o));
                }
            }
            if (g == 0) {
                int b = brow >> 2;
                unsigned* mk = g_maxkd + (size_t)(b * 8 + hh) * HD;
#pragma unroll
                for (int ni = 0; ni < 4; ni++) {
                    atomicMax(&mk[ni * 8 + 2 * t],     fkey(cmax[ni][0]));
                    atomicMax(&mk[ni * 8 + 2 * t + 1], fkey(cmax[ni][1]));
                }
            }
        }
    } else {
#pragma unroll
        for (int mi = 0; mi < 4; mi++) {
            int r0 = brow * 128 + wm * 64 + mi * 16 + g;
            int r1 = r0 + 8;
            int cbase = bcol * 128 + wn * 32;
            const float* in0 = extra + (size_t)r0 * H_ + cbase;
            const float* in1 = extra + (size_t)r1 * H_ + cbase;
            float* o0 = C + (size_t)r0 * H_ + cbase;
            float* o1 = C + (size_t)r1 * H_ + cbase;
#pragma unroll
            for (int ni = 0; ni < 4; ni++) {
                int dcol = ni * 8 + 2 * t;
                float2 i0 = *(const float2*)(in0 + dcol);
                float2 i1 = *(const float2*)(in1 + dcol);
                *(float2*)(o0 + dcol) = make_float2(
                    (dacc[mi][ni][0] + i0.x) * RSQRT2, (dacc[mi][ni][1] + i0.y) * RSQRT2);
                *(float2*)(o1 + dcol) = make_float2(
                    (dacc[mi][ni][2] + i1.x) * RSQRT2, (dacc[mi][ni][3] + i1.y) * RSQRT2);
            }
        }
    }
}

// ---------------- attention: fp16 mma, static bound, 4-stage cp.async,
// ---------------- V natural layout + ldmatrix.trans PV B-frags ----------------
#define ASTR 40

__global__ __launch_bounds__(256) void attn_f16_kernel()
{
    __shared__ __half Ks[4][32 * ASTR];
    __shared__ __half Vs[4][32 * ASTR];

    int tid = threadIdx.x;
    int wid = tid >> 5, lane = tid & 31;
    int g = lane >> 2, t = lane & 3;
    int qhalf = blockIdx.x & 1, bh = blockIdx.x >> 1;
    int b = bh >> 3, h = bh & 7;
    int qbase = qhalf * 256 + wid * 32;

    int brow_lm = (lane & 7) + (lane >> 4) * 8;      // K (non-trans)
    int bcol_lm = ((lane >> 3) & 1) * 8;
    int trow_lm = lane & 15;                         // V (trans): key row
    int tcol_lm = (lane >> 4) * 8;                   // +8 n col

    // Q fragments resident
    const __half* Qg = g_Q + ((size_t)bh * S_ + qbase) * HD;
    unsigned qf[2][2][4];
#pragma unroll
    for (int mi = 0; mi < 2; mi++) {
        int r = mi * 16 + g;
#pragma unroll
        for (int ks = 0; ks < 2; ks++) {
            qf[mi][ks][0] = ldu32(&Qg[r * HD + ks * 16 + 2 * t]);
            qf[mi][ks][1] = ldu32(&Qg[(r + 8) * HD + ks * 16 + 2 * t]);
            qf[mi][ks][2] = ldu32(&Qg[r * HD + ks * 16 + 2 * t + 8]);
            qf[mi][ks][3] = ldu32(&Qg[(r + 8) * HD + ks * 16 + 2 * t + 8]);
        }
    }

    // static row-max bound
    float mrow[4];
    {
        const unsigned* mku = g_maxkd + bh * HD;
        float m0[2] = {0.f, 0.f}, m1[2] = {0.f, 0.f};
#pragma unroll
        for (int ks = 0; ks < 2; ks++) {
            float mkA0 = funkey(mku[ks * 16 + 2 * t]);
            float mkA1 = funkey(mku[ks * 16 + 2 * t + 1]);
            float mkB0 = funkey(mku[ks * 16 + 2 * t + 8]);
            float mkB1 = funkey(mku[ks * 16 + 2 * t + 9]);
#pragma unroll
            for (int mi = 0; mi < 2; mi++) {
                float2 qa = __half22float2(*(__half2*)&qf[mi][ks][0]);
                float2 qb = __half22float2(*(__half2*)&qf[mi][ks][2]);
                float2 qc = __half22float2(*(__half2*)&qf[mi][ks][1]);
                float2 qd = __half22float2(*(__half2*)&qf[mi][ks][3]);
                m0[mi] += qa.x * mkA0 + qa.y * mkA1 + qb.x * mkB0 + qb.y * mkB1;
                m1[mi] += qc.x * mkA0 + qc.y * mkA1 + qd.x * mkB0 + qd.y * mkB1;
            }
        }
#pragma unroll
        for (int o = 1; o <= 2; o <<= 1) {
#pragma unroll
            for (int mi = 0; mi < 2; mi++) {
                m0[mi] += __shfl_xor_sync(0xffffffffu, m0[mi], o);
                m1[mi] += __shfl_xor_sync(0xffffffffu, m1[mi], o);
            }
        }
        mrow[0] = m0[0]; mrow[1] = m1[0]; mrow[2] = m0[1]; mrow[3] = m1[1];
    }

    float oacc[2][4][4];
#pragma unroll
    for (int mi = 0; mi < 2; mi++)
#pragma unroll
        for (int nd = 0; nd < 4; nd++)
#pragma unroll
            for (int c = 0; c < 4; c++) oacc[mi][nd][c] = 0.f;
    float lacc[2][4];
#pragma unroll
    for (int mi = 0; mi < 2; mi++)
#pragma unroll
        for (int c = 0; c < 4; c++) lacc[mi][c] = 0.f;

    const unsigned ONES2[2] = {0x3C003C00u, 0x3C003C00u};

    int mat = tid >> 7;           // 0 = K, 1 = V
    int lrw = (tid >> 2) & 31;
    int c4  = tid & 3;
    const __half* Kg = g_K + (size_t)bh * S_ * HD;
    const __half* Vg = g_V + (size_t)bh * S_ * HD;
    const __half* src = (mat == 0) ? Kg : Vg;
    uint32_t ksb = (uint32_t)__cvta_generic_to_shared(&Ks[0][0]);
    uint32_t vsb = (uint32_t)__cvta_generic_to_shared(&Vs[0][0]);
    uint32_t dstb = (mat == 0) ? ksb : vsb;

#define ASTAGE(kt_) do { \
    uint32_t _soff = (uint32_t)((kt_) & 3) * (32 * ASTR * 2) + (uint32_t)lrw * (ASTR * 2) + (uint32_t)c4 * 16; \
    cp16s(dstb + _soff, src + (size_t)((kt_) * 32 + lrw) * HD + c4 * 8); \
} while (0)

    ASTAGE(0); CP_COMMIT();
    ASTAGE(1); CP_COMMIT();
    ASTAGE(2); CP_COMMIT();

#pragma unroll 4
    for (int kt = 0; kt < 16; kt++) {
        CP_WAIT2();
        __syncthreads();
        if (kt + 3 < 16) ASTAGE(kt + 3);
        CP_COMMIT();

        uint32_t kbuf = ksb + (uint32_t)(kt & 3) * (32 * ASTR * 2);
        uint32_t vbuf = vsb + (uint32_t)(kt & 3) * (32 * ASTR * 2);

        // ---- QK^T with -m folded into accumulator init ----
        float sacc[2][4][4];
#pragma unroll
        for (int mi = 0; mi < 2; mi++)
#pragma unroll
            for (int ni = 0; ni < 4; ni++) {
                sacc[mi][ni][0] = -mrow[2 * mi];
                sacc[mi][ni][1] = -mrow[2 * mi];
                sacc[mi][ni][2] = -mrow[2 * mi + 1];
                sacc[mi][ni][3] = -mrow[2 * mi + 1];
            }

#pragma unroll
        for (int ks = 0; ks < 2; ks++) {
            unsigned kb[4][2];
#pragma unroll
            for (int nig = 0; nig < 2; nig++) {
                unsigned r[4];
                ldsm4(r, kbuf + (uint32_t)((nig * 16 + brow_lm) * ASTR + ks * 16 + bcol_lm) * 2);
                kb[nig * 2][0] = r[0]; kb[nig * 2][1] = r[1];
                kb[nig * 2 + 1][0] = r[2]; kb[nig * 2 + 1][1] = r[3];
            }
#pragma unroll
            for (int mi = 0; mi < 2; mi++)
#pragma unroll
                for (int ni = 0; ni < 4; ni++)
                    mma_f16(sacc[mi][ni], qf[mi][ks], kb[ni]);
        }

        // ---- exp (f16x2); result IS the PV A-frag ----
        unsigned p01[2][4], p23[2][4];
#pragma unroll
        for (int mi = 0; mi < 2; mi++)
#pragma unroll
            for (int ni = 0; ni < 4; ni++) {
                p01[mi][ni] = ex2h2(packh2(sacc[mi][ni][0], sacc[mi][ni][1]));
                p23[mi][ni] = ex2h2(packh2(sacc[mi][ni][2], sacc[mi][ni][3]));
            }

        // ---- PV (ldmatrix.trans B-frags from [s][d] V tile) + l-ones-mma ----
#pragma unroll
        for (int ks = 0; ks < 2; ks++) {
            unsigned vb[4][2];
#pragma unroll
            for (int ng = 0; ng < 2; ng++) {
                unsigned r[4];
                ldsm4t(r, vbuf + (uint32_t)((ks * 16 + trow_lm) * ASTR + ng * 16 + tcol_lm) * 2);
                vb[ng * 2][0] = r[0]; vb[ng * 2][1] = r[1];
                vb[ng * 2 + 1][0] = r[2]; vb[ng * 2 + 1][1] = r[3];
            }
#pragma unroll
            for (int mi = 0; mi < 2; mi++) {
                unsigned pa_[4];
                pa_[0] = p01[mi][2 * ks];
                pa_[1] = p23[mi][2 * ks];
                pa_[2] = p01[mi][2 * ks + 1];
                pa_[3] = p23[mi][2 * ks + 1];
#pragma unroll
                for (int nd = 0; nd < 4; nd++)
                    mma_f16(oacc[mi][nd], pa_, vb[nd]);
                mma_f16(lacc[mi], pa_, ONES2);
            }
        }
    }
#undef ASTAGE

    // finalize
#pragma unroll
    for (int r = 0; r < 4; r++) {
        int mi = r >> 1, cb = (r & 1) * 2;
        float inv = 1.f / lacc[mi][cb];
        int row = qbase + (r >> 1) * 16 + (r & 1) * 8 + g;
        __half* op = g_attn + ((size_t)b * S_ + row) * H_ + h * HD;
#pragma unroll
        for (int nd = 0; nd < 4; nd++) {
            *(__half2*)(op + nd * 8 + 2 * t) = __floats2half2_rn(
                oacc[mi][nd][cb] * inv, oacc[mi][nd][cb + 1] * inv);
        }
    }
}

// ---------------- launch ----------------
extern "C" void kernel_launch(void* const* d_in, const int* in_sizes, int n_in,
                              void* d_out, int out_size)
{
    const float* inputs = (const float*)d_in[0];
    const float* rmask  = (const float*)d_in[1];
    const float* w_in   = (const float*)d_in[2];
    const float* w_out  = (const float*)d_in[3];
    const float* gamma  = (const float*)d_in[4];
    const float* beta   = (const float*)d_in[5];
    float* out = (float*)d_out;

    const int gemm_smem = 6 * TILEH * (int)sizeof(__half);   // 110592 B (3-stage, 2 CTAs/SM)
    cudaFuncSetAttribute(gemm_f16<1>, cudaFuncAttributeMaxDynamicSharedMemorySize, gemm_smem);
    cudaFuncSetAttribute(gemm_f16<2>, cudaFuncAttributeMaxDynamicSharedMemorySize, gemm_smem);

    ln_conv_kernel<<<M_ / 8, 256>>>(inputs, gamma, beta, rmask, w_in, w_out);
    gemm_f16<1><<<dim3(6, M_ / 128), 256, gemm_smem>>>(nullptr, nullptr);
    attn_f16_kernel<<<512, 256>>>();
    gemm_f16<2><<<dim3(2, M_ / 128), 256, gemm_smem>>>(inputs, out);
}